// round 9
// baseline (speedup 1.0000x reference)
#include <cuda_runtime.h>

// ---------------------------------------------------------------------------
// QHashSoftmax: LUT fixed-point softmax, exact-integer reformulation.
//   idx = clamp(rne(x*16), -128, 127) & 255            (cvt.rni.sat.s8)
//   k[idx] = clip(rint(exp(signed(idx)/16 * scale)*128), 0, 127)   (u8 LUT)
//   S = sum(k) over 1024-element row   (exact integer, <= 130048)
//   t = min(floor(S/k), 1023)   (k=0 -> 1023)  [fp32 div+floor exact here]
//   out = g_div_u8[t]/128,  g_div_u8[t] = min(rint(128/t), 127)  (t=0 -> 127)
//
// Structure (R8, warp-autonomous):
//  - 1 warp = 1 row of 1024. Lane l owns float4 l+32j (j=0..7): every
//    LDG/STG is per-instruction fully coalesced (512B/warp/instr).
//  - ONE __reduce_add_sync gives the warp-uniform row sum S: after the smem
//    table init barrier there are NO block barriers, NO atomics.
//  - per-warp ocode[128] built with one exact fp32 div + one tdiv8 gather
//    per entry (4 per lane); reciprocal table is scale-independent, built
//    once in setup.
//  - exp table u8[256] (conflict deg <= 2); ocode u8[128] = 32 words,
//    one/bank -> conflict-FREE gather. .cs streaming hints.
// ---------------------------------------------------------------------------

__device__ unsigned char g_exp_u8[256];    // wrapped-code -> k
__device__ unsigned char g_div_u8[1024];   // t -> output code (scale-indep)

__global__ void qhs_setup_kernel(const float* __restrict__ scale_ptr) {
    int i = threadIdx.x;                       // 0..1023
    if (i < 256) {
        float scale = *scale_ptr;
        int sv = (i >= 128) ? (i - 256) : i;   // two's-complement decode
        float val = (float)sv * 0.0625f * scale;
        double e = exp((double)val);           // high-precision exp
        double r = rint(e * 128.0);            // round half to even
        if (r > 127.0) r = 127.0;
        if (r < 0.0)   r = 0.0;
        g_exp_u8[i] = (unsigned char)(int)r;
    }
    // reciprocal table: t -> clip(rint(128/t), ..., 127); t=0 -> inf -> 127
    double inv = 128.0 / (double)i;            // i=0 -> +inf
    double r2 = rint(inv);
    if (r2 > 127.0) r2 = 127.0;
    g_div_u8[i] = (unsigned char)(int)r2;
}

// clamp(round-half-even(f), -128, 127) & 255 in one convert + one mask
__device__ __forceinline__ unsigned qhs_code(float f) {
    int r;
    asm("cvt.rni.sat.s8.f32 %0, %1;" : "=r"(r) : "f"(f));
    return (unsigned)r & 255u;
}

#define WARPS_PER_BLOCK 8

__global__ __launch_bounds__(256, 6) void qhs_main_kernel(
    const float4* __restrict__ x, float4* __restrict__ out)
{
    __shared__ unsigned char sk8[256];                     // exp codes
    __shared__ unsigned char tdiv8[1024];                  // t -> out code
    __shared__ unsigned char ocode[WARPS_PER_BLOCK][128];  // per-warp, by k

    const int tid  = threadIdx.x;
    const int w    = tid >> 5;
    const int lane = tid & 31;

    sk8[tid] = g_exp_u8[tid];
    ((unsigned*)tdiv8)[tid] = ((const unsigned*)g_div_u8)[tid];
    __syncthreads();          // the ONLY block barrier

    // Warp w owns row (blockIdx.x*8 + w); lane l -> float4 l + 32j.
    const long long base =
        (long long)blockIdx.x * (WARPS_PER_BLOCK * 256) + w * 256 + lane;

    // ---- stream: load -> quantize -> gather k -> dp4a accumulate --------
    unsigned pk[8];
    unsigned s = 0u;
#pragma unroll
    for (int j = 0; j < 8; j++) {
        float4 v = __ldcs(&x[base + j * 32]);
        unsigned p = qhs_code(v.x * 16.0f)
                   | (qhs_code(v.y * 16.0f) << 8)
                   | (qhs_code(v.z * 16.0f) << 16)
                   | (qhs_code(v.w * 16.0f) << 24);
        unsigned k0 = sk8[p & 255u];
        unsigned k1 = sk8[(p >> 8) & 255u];
        unsigned k2 = sk8[(p >> 16) & 255u];
        unsigned k3 = sk8[p >> 24];
        pk[j] = k0 | (k1 << 8) | (k2 << 16) | (k3 << 24);
        s = __dp4a(pk[j], 0x01010101u, s);       // partial <= 4064
    }
    const int S = __reduce_add_sync(0xFFFFFFFFu, (int)s);  // warp-uniform

    // ---- per-warp output-code table (4 entries per lane) ----------------
    const float Sf = (float)S;                   // exact (<= 130048 < 2^18)
#pragma unroll
    for (int kk = lane; kk < 128; kk += 32) {
        // floor(S/k): IEEE div then floor — exact (err < 1/k fractional gap).
        // kk==0 -> +inf -> 1023 (reference e==0 branch). tdiv8 handles t=0.
        float t = fminf(floorf(__fdiv_rn(Sf, (float)kk)), 1023.0f);
        ocode[w][kk] = tdiv8[(int)t];
    }
    __syncwarp();

    // ---- conflict-free byte gathers + coalesced streaming stores --------
#pragma unroll
    for (int j = 0; j < 8; j++) {
        unsigned p = pk[j];
        float4 o;
        o.x = (float)ocode[w][p & 255u]         * 0.0078125f;
        o.y = (float)ocode[w][(p >> 8) & 255u]  * 0.0078125f;
        o.z = (float)ocode[w][(p >> 16) & 255u] * 0.0078125f;
        o.w = (float)ocode[w][p >> 24]          * 0.0078125f;
        __stcs(&out[base + j * 32], o);
    }
}

extern "C" void kernel_launch(void* const* d_in, const int* in_sizes, int n_in,
                              void* d_out, int out_size) {
    const float* x     = (const float*)d_in[0];   // [4,12,1024,1024] fp32
    const float* scale = (const float*)d_in[1];   // scalar fp32

    const int n_elems = in_sizes[0];
    const int n_rows  = n_elems >> 10;                      // rows of 1024
    const int n_blocks = n_rows / WARPS_PER_BLOCK;

    qhs_setup_kernel<<<1, 1024>>>(scale);
    qhs_main_kernel<<<n_blocks, 256>>>((const float4*)x, (float4*)d_out);
}